// round 4
// baseline (speedup 1.0000x reference)
#include <cuda_runtime.h>
#include <cstdint>

// Embedding gather: out[token, :] = embedding[input_ids[token], :]
// input_ids: [4096] int32, embedding: [32000, 1024] fp32, out: [4096, 1024] fp32
//
// One WARP per token; each lane moves 8 float4 (lane + 32*i).
// __launch_bounds__(256, 4) gives a 64-register budget so ptxas can keep all
// 8 LDG.128 in flight (front-batched) before the dependent STG.128 run —
// real MLP=8 per thread, unlike the previous 32-reg-capped version which
// serialized into ld/st pairs.

static constexpr int VEC_PER_ROW = 256;   // 1024 floats / 4
static constexpr int TOKENS_PER_CTA = 8;
static constexpr int VECS_PER_LANE = VEC_PER_ROW / 32;  // 8

__global__ void __launch_bounds__(256, 4)
embed_gather_kernel(const int* __restrict__ ids,
                    const float4* __restrict__ emb,
                    float4* __restrict__ out,
                    int n_tokens)
{
    int token = blockIdx.x * TOKENS_PER_CTA + (threadIdx.x >> 5);
    if (token >= n_tokens) return;
    int lane = threadIdx.x & 31;

    int id = ids[token];   // warp-uniform broadcast load
    const float4* __restrict__ src = emb + (size_t)id * VEC_PER_ROW;
    float4* __restrict__ dst = out + (size_t)token * VEC_PER_ROW;

    // Front-batched independent loads (MLP = 8)
    float4 v0 = src[lane + 0 * 32];
    float4 v1 = src[lane + 1 * 32];
    float4 v2 = src[lane + 2 * 32];
    float4 v3 = src[lane + 3 * 32];
    float4 v4 = src[lane + 4 * 32];
    float4 v5 = src[lane + 5 * 32];
    float4 v6 = src[lane + 6 * 32];
    float4 v7 = src[lane + 7 * 32];

    dst[lane + 0 * 32] = v0;
    dst[lane + 1 * 32] = v1;
    dst[lane + 2 * 32] = v2;
    dst[lane + 3 * 32] = v3;
    dst[lane + 4 * 32] = v4;
    dst[lane + 5 * 32] = v5;
    dst[lane + 6 * 32] = v6;
    dst[lane + 7 * 32] = v7;
}

extern "C" void kernel_launch(void* const* d_in, const int* in_sizes, int n_in,
                              void* d_out, int out_size)
{
    const int*    ids = (const int*)d_in[0];
    const float4* emb = (const float4*)d_in[1];
    float4*       out = (float4*)d_out;

    int n_tokens = in_sizes[0];   // 4096
    int grid = (n_tokens + TOKENS_PER_CTA - 1) / TOKENS_PER_CTA;  // 512
    embed_gather_kernel<<<grid, 256>>>(ids, emb, out, n_tokens);
}

// round 5
// speedup vs baseline: 1.2584x; 1.2584x over previous
#include <cuda_runtime.h>
#include <cstdint>

// Embedding gather: out[token, :] = embedding[input_ids[token], :]
// input_ids: [4096] int32, embedding: [32000, 1024] fp32, out: [4096, 1024] fp32
//
// Single-wave design: grid = 1024 CTAs x 256 threads (<= 148 SMs x 8 resident)
// so there are NO wave transitions. Each CTA handles 4 consecutive tokens;
// each thread moves one float4 per token (256 threads x 16 B = 4 KB row).
// Schedule per thread: 4 independent id loads -> 4 independent row LDG.128
// -> 4 STG.128. ~40 regs, genuinely front-batchable.

static constexpr int VEC_PER_ROW   = 256;  // 1024 floats / 4
static constexpr int TOKENS_PER_CTA = 4;

__global__ void __launch_bounds__(256)
embed_gather_kernel(const int* __restrict__ ids,
                    const float4* __restrict__ emb,
                    float4* __restrict__ out,
                    int n_tokens)
{
    int base = blockIdx.x * TOKENS_PER_CTA;
    int tid  = threadIdx.x;

    // Independent warp-uniform id loads (front-batched)
    int id0 = ids[base + 0];
    int id1 = ids[base + 1];
    int id2 = ids[base + 2];
    int id3 = ids[base + 3];

    // Independent row loads (MLP = 4, different rows)
    float4 v0 = emb[(size_t)id0 * VEC_PER_ROW + tid];
    float4 v1 = emb[(size_t)id1 * VEC_PER_ROW + tid];
    float4 v2 = emb[(size_t)id2 * VEC_PER_ROW + tid];
    float4 v3 = emb[(size_t)id3 * VEC_PER_ROW + tid];

    float4* __restrict__ dst = out + (size_t)base * VEC_PER_ROW + tid;
    dst[0 * VEC_PER_ROW] = v0;
    dst[1 * VEC_PER_ROW] = v1;
    dst[2 * VEC_PER_ROW] = v2;
    dst[3 * VEC_PER_ROW] = v3;
}

extern "C" void kernel_launch(void* const* d_in, const int* in_sizes, int n_in,
                              void* d_out, int out_size)
{
    const int*    ids = (const int*)d_in[0];
    const float4* emb = (const float4*)d_in[1];
    float4*       out = (float4*)d_out;

    int n_tokens = in_sizes[0];   // 4096
    int grid = n_tokens / TOKENS_PER_CTA;   // 1024 — single resident wave
    embed_gather_kernel<<<grid, 256>>>(ids, emb, out, n_tokens);
}